// round 16
// baseline (speedup 1.0000x reference)
#include <cuda_runtime.h>
#include <cuda_fp16.h>
#include <math_constants.h>
#include <cstdint>

#define Np   8192
#define DP   128
#define DM   256
#define BM   8192           // B*M queries
#define NPT  32768          // B*Np distinct points
#define NROW 131072         // BM*16 (query,neighbor) rows
#define RES_ELEMS (BM*DP)

// ===================== PTX helpers (baseline sm_103) =====================
__device__ __forceinline__ uint32_t smem_u32(const void* p) {
    uint32_t a;
    asm("{ .reg .u64 t; cvta.to.shared.u64 t, %1; cvt.u32.u64 %0, t; }" : "=r"(a) : "l"(p));
    return a;
}
__device__ __forceinline__ void cpasync16(uint32_t dst, const void* src) {
    asm volatile("cp.async.cg.shared.global [%0], [%1], 16;" :: "r"(dst), "l"(src));
}
#define CP_COMMIT() asm volatile("cp.async.commit_group;" ::: "memory")
#define CP_WAIT(n)  asm volatile("cp.async.wait_group %0;" :: "n"(n) : "memory")
__device__ __forceinline__ void cp_wait_dyn(int n) {
    switch (n) {
        case 0: CP_WAIT(0); break;
        case 1: CP_WAIT(1); break;
        case 2: CP_WAIT(2); break;
        default: CP_WAIT(3); break;
    }
}

__device__ __forceinline__ void ldsm4(uint32_t* r, uint32_t addr) {
    asm volatile("ldmatrix.sync.aligned.m8n8.x4.shared.b16 {%0,%1,%2,%3}, [%4];"
        : "=r"(r[0]), "=r"(r[1]), "=r"(r[2]), "=r"(r[3]) : "r"(addr));
}
__device__ __forceinline__ void mma16816(float* c, const uint32_t* a, const uint32_t* b) {
    asm volatile("mma.sync.aligned.m16n8k16.row.col.f32.f16.f16.f32 "
        "{%0,%1,%2,%3}, {%4,%5,%6,%7}, {%8,%9}, {%0,%1,%2,%3};"
        : "+f"(c[0]), "+f"(c[1]), "+f"(c[2]), "+f"(c[3])
        : "r"(a[0]), "r"(a[1]), "r"(a[2]), "r"(a[3]), "r"(b[0]), "r"(b[1]));
}

// ===================== scratch =====================
__device__ int   g_knn[BM*16];
__device__ float g_Q2 [BM*DM];          // qf @ (wq@g1)
__device__ float g_K2 [NPT*DM];         // x @ (wk@g1)
__device__ float g_vpt[NPT*DM];
__device__ float g_bg [DM];             // d2b@g1 + g1b
__device__ __align__(16) __half g_qf [BM*DP];
__device__ __align__(16) __half g_fs [NPT*DP];
__device__ __align__(16) __half g_xp [NPT*DM];
// transposed fp16 weights [N=256][K]
__device__ __align__(16) __half w_f1 [DM*DP];
__device__ __align__(16) __half w_v  [DM*DM];
__device__ __align__(16) __half w_d2 [DM*DM];
__device__ __align__(16) __half w_g2 [DM*DM];
__device__ __align__(16) __half w_qg1[DM*DP];   // (wq@g1)^T
__device__ __align__(16) __half w_kg1[DM*DM];   // (wk@g1)^T
__device__ __align__(16) __half w_d2g1[DM*DM];  // (d2@g1)^T

// ===================== KNN =====================
__global__ void knn_kernel(const float* __restrict__ xyz,
                           const float* __restrict__ query) {
    int wip  = threadIdx.x >> 5;
    int lane = threadIdx.x & 31;
    int qi   = blockIdx.x * 8 + wip;
    int b    = qi >> 11;
    const float* qp = query + (size_t)qi * 131;
    float qx = qp[0], qy = qp[1], qz = qp[2];
    float q2 = qx*qx + qy*qy + qz*qz;
    const float* xb = xyz + (size_t)b * Np * 3;

    float bd[16]; int bi[16];
#pragma unroll
    for (int i = 0; i < 16; i++) { bd[i] = CUDART_INF_F; bi[i] = 0x7fffffff; }
    float cm = CUDART_INF_F; int cmp_ = 0;

    for (int n = lane; n < Np; n += 32) {
        float x = xb[3*n], y = xb[3*n+1], z = xb[3*n+2];
        float d = q2 + (x*x + y*y + z*z) - 2.0f*(qx*x + qy*y + qz*z);
        if (d < cm) {
#pragma unroll
            for (int i = 0; i < 16; i++) if (i == cmp_) { bd[i] = d; bi[i] = n; }
            cm = -CUDART_INF_F;
#pragma unroll
            for (int i = 0; i < 16; i++) if (bd[i] > cm) { cm = bd[i]; cmp_ = i; }
        }
    }
    for (int r = 0; r < 16; r++) {
        float md = CUDART_INF_F; int mi = 0x7fffffff;
#pragma unroll
        for (int i = 0; i < 16; i++) {
            float d = bd[i]; int id = bi[i];
            if (d < md || (d == md && id < mi)) { md = d; mi = id; }
        }
#pragma unroll
        for (int off = 16; off > 0; off >>= 1) {
            float od = __shfl_down_sync(0xffffffffu, md, off);
            int   oi = __shfl_down_sync(0xffffffffu, mi, off);
            if (od < md || (od == md && oi < mi)) { md = od; mi = oi; }
        }
        int w = __shfl_sync(0xffffffffu, mi, 0);
        if (lane == 0) g_knn[qi*16 + r] = w;
#pragma unroll
        for (int i = 0; i < 16; i++) if (bi[i] == w) bd[i] = CUDART_INF_F;
    }
}

// ===================== weight transpose (fc1, wv, d2, g2) ==================
__global__ void wprep_all(const float* __restrict__ fc1w, const float* __restrict__ wv,
                          const float* __restrict__ d2w,  const float* __restrict__ g2w) {
    int i = blockIdx.x * 256 + threadIdx.x;
    if (i < 32768) {                       // fc1: K=128
        int k = i / DM, n = i % DM;
        w_f1[n*DP + k] = __float2half_rn(fc1w[i]);
    } else if (i < 98304) {                // wv
        int j = i - 32768, k = j / DM, n = j % DM;
        w_v[n*DM + k] = __float2half_rn(wv[j]);
    } else if (i < 163840) {               // d2
        int j = i - 98304, k = j / DM, n = j % DM;
        w_d2[n*DM + k] = __float2half_rn(d2w[j]);
    } else if (i < 229376) {               // g2
        int j = i - 163840, k = j / DM, n = j % DM;
        w_g2[n*DM + k] = __float2half_rn(g2w[j]);
    }
}

// ===================== fused weight products ===============================
// blk 0..255:  d2g1[n], + bg[n];  blk 256..511: wkg1[n];  blk 512..767: wqg1[n]
__global__ __launch_bounds__(256) void wfuse_kernel(
    const float* __restrict__ d2w, const float* __restrict__ d2b,
    const float* __restrict__ wk,  const float* __restrict__ wq,
    const float* __restrict__ g1w, const float* __restrict__ g1b) {
    __shared__ float g1col[DM];
    int blk = blockIdx.x, tid = threadIdx.x;
    int n = blk & 255;
    g1col[tid] = g1w[tid*DM + n];
    __syncthreads();
    if (blk < 256) {
        float acc = 0.f;
        const float* row = d2w + tid*DM;
#pragma unroll 8
        for (int j = 0; j < DM; j++) acc = fmaf(row[j], g1col[j], acc);
        w_d2g1[n*DM + tid] = __float2half_rn(acc);
        if (tid == 0) {
            float bacc = g1b[n];
            for (int j = 0; j < DM; j++) bacc = fmaf(d2b[j], g1col[j], bacc);
            g_bg[n] = bacc;
        }
    } else if (blk < 512) {
        float acc = 0.f;
        const float* row = wk + tid*DM;
#pragma unroll 8
        for (int j = 0; j < DM; j++) acc = fmaf(row[j], g1col[j], acc);
        w_kg1[n*DM + tid] = __float2half_rn(acc);
    } else {
        if (tid < DP) {
            float acc = 0.f;
            const float* row = wq + tid*DM;
#pragma unroll 8
            for (int j = 0; j < DM; j++) acc = fmaf(row[j], g1col[j], acc);
            w_qg1[n*DP + tid] = __float2half_rn(acc);
        }
    }
}

// ===================== activation converts =====================
__global__ void cvt_kernel(const float* __restrict__ query,
                           const float* __restrict__ feat) {
    int i = blockIdx.x * 256 + threadIdx.x;
    if (i < BM*DP) {
        int r = i >> 7, c = i & 127;
        g_qf[i] = __float2half_rn(query[(size_t)r*131 + 3 + c]);
    } else {
        int j = i - BM*DP;
        g_fs[j] = __float2half_rn(feat[j]);
    }
}

// ===================== GEMM machinery (fp16, 1-term) =====================
#define B_OFF  18432
#define STG    55296
#define SMEM_TOTAL 221184

__device__ __forceinline__ void load_chunk(uint32_t sbase,
    const __half* A, const __half* B,
    int tile, int Kdim, int kc0, int tid)
{
    {
        int e = tid;
        int r = e >> 3, c = e & 7;
        size_t off = (size_t)(tile*128 + r)*Kdim + kc0 + c*8;
        cpasync16(sbase + r*144 + c*16, A + off);
        e = tid + 512; r = e >> 3; c = e & 7;
        off = (size_t)(tile*128 + r)*Kdim + kc0 + c*8;
        cpasync16(sbase + r*144 + c*16, A + off);
    }
#pragma unroll
    for (int g = 0; g < 4; g++) {
        int e = g*512 + tid;
        int n = e >> 3, c = e & 7;
        size_t off = (size_t)n*Kdim + kc0 + c*8;
        cpasync16(sbase + B_OFF + n*144 + c*16, B + off);
    }
}

__device__ __forceinline__ void load_b2(uint32_t bbase,
    const __half* B, int kc0, int tid)
{
#pragma unroll
    for (int g = 0; g < 4; g++) {
        int e = g*512 + tid;
        int n = e >> 3, c = e & 7;
        size_t off = (size_t)n*DM + kc0 + c*8;
        cpasync16(bbase + n*144 + c*16, B + off);
    }
}

__device__ __forceinline__ void mma_chunk(uint32_t aB, uint32_t bB,
    uint32_t aRow, uint32_t aKoff, uint32_t bRow, uint32_t bKoff,
    int nbase, float (*acc)[8][4])
{
#pragma unroll
    for (int k16 = 0; k16 < 4; k16++) {
        uint32_t ah[2][4];
        uint32_t ab = aB + aRow*144 + k16*32 + aKoff;
        ldsm4(ah[0], ab);
        ldsm4(ah[1], ab + 16*144);
#pragma unroll
        for (int np = 0; np < 4; np++) {
            uint32_t bh[4];
            ldsm4(bh, bB + (nbase + np*16 + bRow)*144 + k16*32 + bKoff);
#pragma unroll
            for (int mf = 0; mf < 2; mf++) {
                mma16816(acc[mf][2*np],   ah[mf], bh);
                mma16816(acc[mf][2*np+1], ah[mf], bh + 2);
            }
        }
    }
}

// ===================== generic GEMM (Q2 / x / K2 / V) ======================
// epi: 0 = fp32 -> outf; 1 = half(+bias) -> outh
__global__ __launch_bounds__(512, 1) void tc_gemm(
    const __half* __restrict__ A, const __half* __restrict__ Bw,
    const float* __restrict__ bias,
    float* __restrict__ outf, __half* __restrict__ outh,
    int Kdim, int epi_mode)
{
    extern __shared__ char dsm[];
    uint32_t sb = smem_u32(dsm);
    int tid = threadIdx.x, lid = tid & 31, wid = tid >> 5;
    int tile = blockIdx.x;
    int mw = wid & 3, nw = wid >> 2;
    int mbase = mw*32, nbase = nw*64;

    uint32_t aRow  = mbase + (lid & 15);
    uint32_t aKoff = ((lid >> 4) & 1) * 16;
    uint32_t bRow  = (lid & 7) + ((lid >> 4) & 1) * 8;
    uint32_t bKoff = ((lid >> 3) & 1) * 16;

    float acc[2][8][4];
#pragma unroll
    for (int i = 0; i < 2; i++)
#pragma unroll
        for (int j = 0; j < 8; j++)
#pragma unroll
            for (int e = 0; e < 4; e++) acc[i][j][e] = 0.f;

    const int nst = Kdim >> 6;
    int pre = nst < 3 ? nst : 3;
    for (int i = 0; i < pre; i++) {
        load_chunk(sb + i*STG, A, Bw, tile, Kdim, i*64, tid);
        CP_COMMIT();
    }
    for (int s = 0; s < nst; s++) {
        if (s + 3 < nst) {
            load_chunk(sb + ((s+3)&3)*STG, A, Bw, tile, Kdim, (s+3)*64, tid);
            CP_COMMIT();
            cp_wait_dyn(3);
        } else {
            cp_wait_dyn(nst - 1 - s);
        }
        __syncthreads();
        uint32_t stb = sb + (s&3)*STG;
        mma_chunk(stb, stb + B_OFF, aRow, aKoff, bRow, bKoff, nbase, acc);
        __syncthreads();
    }

    float* eb = (float*)dsm;   // [128][264]
#pragma unroll
    for (int mf = 0; mf < 2; mf++)
#pragma unroll
        for (int nf = 0; nf < 8; nf++) {
            int m = mbase + mf*16 + (lid >> 2);
            int n = nbase + nf*8 + (lid & 3)*2;
            eb[m*264 + n]     = acc[mf][nf][0];
            eb[m*264 + n + 1] = acc[mf][nf][1];
            eb[(m+8)*264 + n]     = acc[mf][nf][2];
            eb[(m+8)*264 + n + 1] = acc[mf][nf][3];
        }
    __syncthreads();

    for (int i = tid; i < 128*256; i += 512) {
        int row = i >> 8, col = i & 255;
        float v = eb[row*264 + col];
        if (bias) v += bias[col];
        size_t o = (size_t)(tile*128 + row) * DM + col;
        if (epi_mode == 0) outf[o] = v;
        else               outh[o] = __float2half_rn(v);
    }
}

// ===================== MEGA: h-gen -> pos -> C2 -> t -> attn/out ===========
// smem: A slots 4x18432 [0,73728); B dbl 2x36864 [73728,147456);
//       pos half [128][272] @147456 (69632); sidx @217088 (512); sdel @217600 (2048)
// eb16 (C2 stage) half [128][264] @73728 (67584, over B region - B dead)
// final: ebf fp32 [128][264] @0 (135168); sres @135168 (8192)
#define MG_POS  147456
#define MG_SIDX 217088
#define MG_SDEL 217600
#define MG_EB16 73728

__global__ __launch_bounds__(512, 1) void mega_kernel(
    const float* __restrict__ xyz, const float* __restrict__ query,
    const float* __restrict__ d1w, const float* __restrict__ d1b,
    const float* __restrict__ d2b,
    const float* __restrict__ g2b,
    const float* __restrict__ fc2w, const float* __restrict__ fc2b,
    float* __restrict__ out)
{
    extern __shared__ char dsm[];
    uint32_t sb = smem_u32(dsm);
    int tid = threadIdx.x, lid = tid & 31, wid = tid >> 5;
    int tile = blockIdx.x;
    int bm0 = tile * 8, b = bm0 >> 11;
    int mw = wid & 3, nw = wid >> 2;
    int mbase = mw*32, nbase = nw*64;

    uint32_t aRow  = mbase + (lid & 15);
    uint32_t aKoff = ((lid >> 4) & 1) * 16;
    uint32_t bRow  = (lid & 7) + ((lid >> 4) & 1) * 8;
    uint32_t bKoff = ((lid >> 3) & 1) * 16;

    int*   sidx = (int*)(dsm + MG_SIDX);
    float* sdel = (float*)(dsm + MG_SDEL);   // [128][4]

    // prefetch B(d2) chunks 0,1 (overlaps h generation)
    load_b2(sb + 73728,         w_d2, 0,  tid); CP_COMMIT();
    load_b2(sb + 73728 + 36864, w_d2, 64, tid); CP_COMMIT();

    if (tid < 128) sidx[tid] = g_knn[(bm0 + (tid >> 4))*16 + (tid & 15)];
    __syncthreads();
    if (tid < 128) {
        int r = tid, bm = bm0 + (r >> 4);
        const float* qp = query + (size_t)bm*131;
        const float* xp = xyz + ((size_t)b*Np + sidx[r])*3;
        sdel[r*4+0] = qp[0] - xp[0];
        sdel[r*4+1] = qp[1] - xp[1];
        sdel[r*4+2] = qp[2] - xp[2];
    }
    __syncthreads();

    // generate h = relu(delta@d1 + d1b) directly into A slots (fp16)
    for (int i = tid; i < 128*256; i += 512) {
        int row = i >> 8, col = i & 255;
        float v = fmaf(sdel[row*4+2], d1w[512+col],
                  fmaf(sdel[row*4+1], d1w[256+col],
                  fmaf(sdel[row*4+0], d1w[col], d1b[col])));
        v = fmaxf(v, 0.f);
        int slot = col >> 6;
        *(__half*)(dsm + slot*18432 + row*144 + (col & 63)*2) = __float2half_rn(v);
    }
    __syncthreads();

    float acc[2][8][4];
#pragma unroll
    for (int i = 0; i < 2; i++)
#pragma unroll
        for (int j = 0; j < 8; j++)
#pragma unroll
            for (int e = 0; e < 4; e++) acc[i][j][e] = 0.f;

    // ---------------- loop1: pos = h @ d2 ----------------
    for (int c4 = 0; c4 < 4; c4++) {
        if (c4 < 3) { CP_WAIT(1); } else { CP_WAIT(0); }
        __syncthreads();
        mma_chunk(sb + c4*18432, sb + 73728 + (c4&1)*36864,
                  aRow, aKoff, bRow, bKoff, nbase, acc);
        __syncthreads();
        if (c4 + 2 < 4) {
            load_b2(sb + 73728 + (c4&1)*36864, w_d2, (c4+2)*64, tid);
            CP_COMMIT();
        } else {
            // prefetch d2g1 chunk (c4-2) into the buffer just consumed
            load_b2(sb + 73728 + (c4&1)*36864, w_d2g1, (c4-2)*64, tid);
            CP_COMMIT();
        }
    }

    // stage pos (+d2b) to smem fp16 [128][272]
#pragma unroll
    for (int mf = 0; mf < 2; mf++)
#pragma unroll
        for (int nf = 0; nf < 8; nf++) {
            int m = mbase + mf*16 + (lid >> 2);
            int n = nbase + nf*8 + (lid & 3)*2;
            float b0 = d2b[n], b1 = d2b[n+1];
            __half2 hp;
            hp.x = __float2half_rn(acc[mf][nf][0] + b0);
            hp.y = __float2half_rn(acc[mf][nf][1] + b1);
            *(uint32_t*)(dsm + MG_POS + m*544 + n*2) = *(uint32_t*)&hp;
            hp.x = __float2half_rn(acc[mf][nf][2] + b0);
            hp.y = __float2half_rn(acc[mf][nf][3] + b1);
            *(uint32_t*)(dsm + MG_POS + (m+8)*544 + n*2) = *(uint32_t*)&hp;
        }
#pragma unroll
    for (int i = 0; i < 2; i++)
#pragma unroll
        for (int j = 0; j < 8; j++)
#pragma unroll
            for (int e = 0; e < 4; e++) acc[i][j][e] = 0.f;

    // ---------------- loop2: C2 = h @ d2g1 ----------------
    for (int c4 = 0; c4 < 4; c4++) {
        if (c4 < 3) { CP_WAIT(1); } else { CP_WAIT(0); }
        __syncthreads();
        mma_chunk(sb + c4*18432, sb + 73728 + (c4&1)*36864,
                  aRow, aKoff, bRow, bKoff, nbase, acc);
        __syncthreads();
        if (c4 + 2 < 4) {
            load_b2(sb + 73728 + (c4&1)*36864, w_d2g1, (c4+2)*64, tid);
            CP_COMMIT();
        }
    }

    // stage C2 -> eb16 (over dead B region)
#pragma unroll
    for (int mf = 0; mf < 2; mf++)
#pragma unroll
        for (int nf = 0; nf < 8; nf++) {
            int m = mbase + mf*16 + (lid >> 2);
            int n = nbase + nf*8 + (lid & 3)*2;
            __half2 hp;
            hp.x = __float2half_rn(acc[mf][nf][0]);
            hp.y = __float2half_rn(acc[mf][nf][1]);
            *(uint32_t*)(dsm + MG_EB16 + m*528 + n*2) = *(uint32_t*)&hp;
            hp.x = __float2half_rn(acc[mf][nf][2]);
            hp.y = __float2half_rn(acc[mf][nf][3]);
            *(uint32_t*)(dsm + MG_EB16 + (m+8)*528 + n*2) = *(uint32_t*)&hp;
        }
    __syncthreads();

    // t = relu(C2 + Q2[bm] - K2[pt] + bg) -> fp16 into A slots
    for (int i = tid; i < 128*256; i += 512) {
        int row = i >> 8, col = i & 255;
        float v = __half2float(*(__half*)(dsm + MG_EB16 + row*528 + col*2));
        int bm = bm0 + (row >> 4);
        int idx = sidx[row];
        v += g_Q2[(size_t)bm*DM + col]
           - g_K2[((size_t)b*Np + idx)*DM + col]
           + g_bg[col];
        v = fmaxf(v, 0.f);
        int slot = col >> 6;
        *(__half*)(dsm + slot*18432 + row*144 + (col & 63)*2) = __float2half_rn(v);
    }
    __syncthreads();

    // prefetch g2 chunks 0,1 (over dead eb16/B region)
    load_b2(sb + 73728,         w_g2, 0,  tid); CP_COMMIT();
    load_b2(sb + 73728 + 36864, w_g2, 64, tid); CP_COMMIT();

#pragma unroll
    for (int i = 0; i < 2; i++)
#pragma unroll
        for (int j = 0; j < 8; j++)
#pragma unroll
            for (int e = 0; e < 4; e++) acc[i][j][e] = 0.f;

    // ---------------- loop3: attn_pre = t @ g2 ----------------
    for (int c4 = 0; c4 < 4; c4++) {
        if (c4 < 3) { CP_WAIT(1); } else { CP_WAIT(0); }
        __syncthreads();
        mma_chunk(sb + c4*18432, sb + 73728 + (c4&1)*36864,
                  aRow, aKoff, bRow, bKoff, nbase, acc);
        __syncthreads();
        if (c4 + 2 < 4) {
            load_b2(sb + 73728 + (c4&1)*36864, w_g2, (c4+2)*64, tid);
            CP_COMMIT();
        }
    }

    // ---------------- final epilogue ----------------
    float* ebf  = (float*)dsm;                 // [128][264]
    float* sres = (float*)(dsm + 135168);      // [8][256]
#pragma unroll
    for (int mf = 0; mf < 2; mf++)
#pragma unroll
        for (int nf = 0; nf < 8; nf++) {
            int m = mbase + mf*16 + (lid >> 2);
            int n = nbase + nf*8 + (lid & 3)*2;
            ebf[m*264 + n]     = acc[mf][nf][0];
            ebf[m*264 + n + 1] = acc[mf][nf][1];
            ebf[(m+8)*264 + n]     = acc[mf][nf][2];
            ebf[(m+8)*264 + n + 1] = acc[mf][nf][3];
        }
    __syncthreads();

    {
        int qq = tid >> 6, c0 = tid & 63;
        int bm = bm0 + qq;
        float* attn_out = out + RES_ELEMS + (size_t)bm*16*DM;
#pragma unroll
        for (int jj = 0; jj < 4; jj++) {
            int col = c0 + 64*jj;
            float bb = g2b[col];
            float ap[16];
#pragma unroll
            for (int j = 0; j < 16; j++)
                ap[j] = (ebf[(qq*16 + j)*264 + col] + bb) * 0.0625f;
            float mx = ap[0];
#pragma unroll
            for (int j = 1; j < 16; j++) mx = fmaxf(mx, ap[j]);
            float s = 0.f;
#pragma unroll
            for (int j = 0; j < 16; j++) { ap[j] = __expf(ap[j] - mx); s += ap[j]; }
            float inv = 1.0f / s;
            float racc = 0.f;
#pragma unroll
            for (int j = 0; j < 16; j++) {
                float a = ap[j] * inv;
                attn_out[j*DM + col] = a;
                float vv = g_vpt[((size_t)b*Np + sidx[qq*16 + j])*DM + col];
                float pp = __half2float(*(__half*)(dsm + MG_POS + (qq*16 + j)*544 + col*2));
                racc = fmaf(a, vv + pp, racc);
            }
            sres[qq*256 + col] = racc;
        }
    }
    __syncthreads();

    for (int o = tid; o < 8*DP; o += 512) {
        int qq = o >> 7, c = o & 127;
        float acc2 = fc2b[c];
        const float* sr = sres + qq*256;
#pragma unroll 4
        for (int k = 0; k < DM; k++) acc2 = fmaf(sr[k], fc2w[k*DP + c], acc2);
        int bm = bm0 + qq;
        out[(size_t)bm*DP + c] = acc2 + query[(size_t)bm*131 + 3 + c];
    }
}

// ===================== launch =====================
extern "C" void kernel_launch(void* const* d_in, const int* in_sizes, int n_in,
                              void* d_out, int out_size) {
    const float* xyz   = (const float*)d_in[0];
    const float* feat  = (const float*)d_in[1];
    const float* query = (const float*)d_in[2];
    const float* fc1w  = (const float*)d_in[3];
    const float* fc1b  = (const float*)d_in[4];
    const float* fc2w  = (const float*)d_in[5];
    const float* fc2b  = (const float*)d_in[6];
    const float* d1w   = (const float*)d_in[7];
    const float* d1b   = (const float*)d_in[8];
    const float* d2w   = (const float*)d_in[9];
    const float* d2b   = (const float*)d_in[10];
    const float* g1w   = (const float*)d_in[11];
    const float* g1b   = (const float*)d_in[12];
    const float* g2w   = (const float*)d_in[13];
    const float* g2b   = (const float*)d_in[14];
    const float* wq    = (const float*)d_in[15];
    const float* wk    = (const float*)d_in[16];
    const float* wv    = (const float*)d_in[17];
    float* out = (float*)d_out;

    static int smem_set = 0;
    if (!smem_set) {
        cudaFuncSetAttribute(tc_gemm,     cudaFuncAttributeMaxDynamicSharedMemorySize, SMEM_TOTAL);
        cudaFuncSetAttribute(mega_kernel, cudaFuncAttributeMaxDynamicSharedMemorySize, SMEM_TOTAL);
        smem_set = 1;
    }

    __half *p_f1, *p_v, *p_qg1, *p_kg1, *p_qf, *p_fs, *p_xp;
    float  *p_Q2, *p_K2, *p_vp;
    cudaGetSymbolAddress((void**)&p_f1,  w_f1);
    cudaGetSymbolAddress((void**)&p_v,   w_v);
    cudaGetSymbolAddress((void**)&p_qg1, w_qg1);
    cudaGetSymbolAddress((void**)&p_kg1, w_kg1);
    cudaGetSymbolAddress((void**)&p_qf,  g_qf);
    cudaGetSymbolAddress((void**)&p_fs,  g_fs);
    cudaGetSymbolAddress((void**)&p_xp,  g_xp);
    cudaGetSymbolAddress((void**)&p_Q2,  g_Q2);
    cudaGetSymbolAddress((void**)&p_K2,  g_K2);
    cudaGetSymbolAddress((void**)&p_vp,  g_vpt);

    // launch order tuned so ncu (-s 5 -c 1) captures the x tc_gemm
    knn_kernel   <<<BM/8, 256>>>(xyz, query);                       // 0
    wprep_all    <<<896, 256>>>(fc1w, wv, d2w, g2w);                // 1
    wfuse_kernel <<<768, 256>>>(d2w, d2b, wk, wq, g1w, g1b);        // 2
    cvt_kernel   <<<(BM*DP + NPT*DP)/256, 256>>>(query, feat);      // 3
    // Q2 = qf @ wqg1                     (8192 rows, fp32)
    tc_gemm<<<BM/128, 512, SMEM_TOTAL>>>(p_qf, p_qg1,               // 4
        nullptr, p_Q2, nullptr, DP, 0);
    // x = fs @ fc1 + b                   (32768 rows, half)
    tc_gemm<<<NPT/128, 512, SMEM_TOTAL>>>(p_fs, p_f1,               // 5 <- ncu
        fc1b, nullptr, p_xp, DP, 1);
    // K2 = x @ wkg1                      (32768 rows, fp32)
    tc_gemm<<<NPT/128, 512, SMEM_TOTAL>>>(p_xp, p_kg1,              // 6
        nullptr, p_K2, nullptr, DM, 0);
    // V = x @ wv                         (32768 rows, fp32)
    tc_gemm<<<NPT/128, 512, SMEM_TOTAL>>>(p_xp, p_v,                // 7
        nullptr, p_vp, nullptr, DM, 0);
    // mega: h-gen; pos=h@d2; C2=h@d2g1; t=relu(C2+Q2-K2+bg); attn=t@g2; out
    mega_kernel<<<NROW/128, 512, SMEM_TOTAL>>>(xyz, query,          // 8
        d1w, d1b, d2b, g2b, fc2w, fc2b, out);
}

// round 17
// speedup vs baseline: 1.2127x; 1.2127x over previous
#include <cuda_runtime.h>
#include <cuda_fp16.h>
#include <math_constants.h>
#include <cstdint>

#define Np   8192
#define DP   128
#define DM   256
#define BM   8192           // B*M queries
#define NPT  32768          // B*Np distinct points
#define NROW 131072         // BM*16 (query,neighbor) rows
#define RES_ELEMS (BM*DP)

// ===================== PTX helpers (baseline sm_103) =====================
__device__ __forceinline__ uint32_t smem_u32(const void* p) {
    uint32_t a;
    asm("{ .reg .u64 t; cvta.to.shared.u64 t, %1; cvt.u32.u64 %0, t; }" : "=r"(a) : "l"(p));
    return a;
}
__device__ __forceinline__ void cpasync16(uint32_t dst, const void* src) {
    asm volatile("cp.async.cg.shared.global [%0], [%1], 16;" :: "r"(dst), "l"(src));
}
#define CP_COMMIT() asm volatile("cp.async.commit_group;" ::: "memory")
#define CP_WAIT(n)  asm volatile("cp.async.wait_group %0;" :: "n"(n) : "memory")
__device__ __forceinline__ void cp_wait_dyn(int n) {
    switch (n) {
        case 0: CP_WAIT(0); break;
        case 1: CP_WAIT(1); break;
        case 2: CP_WAIT(2); break;
        default: CP_WAIT(3); break;
    }
}

__device__ __forceinline__ void ldsm4(uint32_t* r, uint32_t addr) {
    asm volatile("ldmatrix.sync.aligned.m8n8.x4.shared.b16 {%0,%1,%2,%3}, [%4];"
        : "=r"(r[0]), "=r"(r[1]), "=r"(r[2]), "=r"(r[3]) : "r"(addr));
}
__device__ __forceinline__ void mma16816(float* c, const uint32_t* a, const uint32_t* b) {
    asm volatile("mma.sync.aligned.m16n8k16.row.col.f32.f16.f16.f32 "
        "{%0,%1,%2,%3}, {%4,%5,%6,%7}, {%8,%9}, {%0,%1,%2,%3};"
        : "+f"(c[0]), "+f"(c[1]), "+f"(c[2]), "+f"(c[3])
        : "r"(a[0]), "r"(a[1]), "r"(a[2]), "r"(a[3]), "r"(b[0]), "r"(b[1]));
}

// ===================== scratch =====================
__device__ int   g_knn[BM*16];
__device__ float g_q  [BM*DM];
__device__ float g_kpt[NPT*DM];
__device__ float g_vpt[NPT*DM];
__device__ __align__(16) __half g_pos[NROW*DM];
__device__ __align__(16) __half g_qf [BM*DP];
__device__ __align__(16) __half g_fs [NPT*DP];
__device__ __align__(16) __half g_xp [NPT*DM];
__device__ __align__(16) __half g_a  [NROW*DM];
// transposed fp16 weights [N=256][K]
__device__ __align__(16) __half w_q [DM*DP];
__device__ __align__(16) __half w_f1[DM*DP];
__device__ __align__(16) __half w_k [DM*DM];
__device__ __align__(16) __half w_v [DM*DM];
__device__ __align__(16) __half w_d2[DM*DM];
__device__ __align__(16) __half w_g1[DM*DM];
__device__ __align__(16) __half w_g2[DM*DM];

// ===================== KNN =====================
__global__ void knn_kernel(const float* __restrict__ xyz,
                           const float* __restrict__ query) {
    int wip  = threadIdx.x >> 5;
    int lane = threadIdx.x & 31;
    int qi   = blockIdx.x * 8 + wip;
    int b    = qi >> 11;
    const float* qp = query + (size_t)qi * 131;
    float qx = qp[0], qy = qp[1], qz = qp[2];
    float q2 = qx*qx + qy*qy + qz*qz;
    const float* xb = xyz + (size_t)b * Np * 3;

    float bd[16]; int bi[16];
#pragma unroll
    for (int i = 0; i < 16; i++) { bd[i] = CUDART_INF_F; bi[i] = 0x7fffffff; }
    float cm = CUDART_INF_F; int cmp_ = 0;

    for (int n = lane; n < Np; n += 32) {
        float x = xb[3*n], y = xb[3*n+1], z = xb[3*n+2];
        float d = q2 + (x*x + y*y + z*z) - 2.0f*(qx*x + qy*y + qz*z);
        if (d < cm) {
#pragma unroll
            for (int i = 0; i < 16; i++) if (i == cmp_) { bd[i] = d; bi[i] = n; }
            cm = -CUDART_INF_F;
#pragma unroll
            for (int i = 0; i < 16; i++) if (bd[i] > cm) { cm = bd[i]; cmp_ = i; }
        }
    }
    for (int r = 0; r < 16; r++) {
        float md = CUDART_INF_F; int mi = 0x7fffffff;
#pragma unroll
        for (int i = 0; i < 16; i++) {
            float d = bd[i]; int id = bi[i];
            if (d < md || (d == md && id < mi)) { md = d; mi = id; }
        }
#pragma unroll
        for (int off = 16; off > 0; off >>= 1) {
            float od = __shfl_down_sync(0xffffffffu, md, off);
            int   oi = __shfl_down_sync(0xffffffffu, mi, off);
            if (od < md || (od == md && oi < mi)) { md = od; mi = oi; }
        }
        int w = __shfl_sync(0xffffffffu, mi, 0);
        if (lane == 0) g_knn[qi*16 + r] = w;
#pragma unroll
        for (int i = 0; i < 16; i++) if (bi[i] == w) bd[i] = CUDART_INF_F;
    }
}

// ===================== prep kernels =====================
__global__ void wprep_kernel(const float* __restrict__ W,
                             __half* __restrict__ T, int K) {
    int i = blockIdx.x * 256 + threadIdx.x;
    if (i >= K * DM) return;
    int k = i / DM, n = i % DM;
    T[n*K + k] = __float2half_rn(W[i]);
}

__global__ void qcvt_kernel(const float* __restrict__ query,
                            __half* __restrict__ qh) {
    int i = blockIdx.x * 256 + threadIdx.x;
    int r = i >> 7, c = i & 127;
    qh[i] = __float2half_rn(query[(size_t)r*131 + 3 + c]);
}

__global__ void fcvt_kernel(const float* __restrict__ feat,
                            __half* __restrict__ fh) {
    int i = blockIdx.x * 256 + threadIdx.x;
    fh[i] = __float2half_rn(feat[i]);
}

// ===================== shared GEMM machinery (fp16, 1-term) ================
// stage: A +0 (18432 = 128 rows x 144B), B +18432 (36864 = 256 rows x 144B)
#define B_OFF  18432
#define STG    55296
#define SMEM_TOTAL 221184
// g1g2 loop2 / posh: 4 t/h-slots (18432 each) at c*18432; B dbl-buf at:
#define SM_B2  73728

__device__ __forceinline__ void load_chunk(uint32_t sbase,
    const __half* A, const __half* B,
    int tile, int Kdim, int kc0, int tid)
{
    {
        int e = tid;
        int r = e >> 3, c = e & 7;
        size_t off = (size_t)(tile*128 + r)*Kdim + kc0 + c*8;
        cpasync16(sbase + r*144 + c*16, A + off);
        e = tid + 512; r = e >> 3; c = e & 7;
        off = (size_t)(tile*128 + r)*Kdim + kc0 + c*8;
        cpasync16(sbase + r*144 + c*16, A + off);
    }
#pragma unroll
    for (int g = 0; g < 4; g++) {
        int e = g*512 + tid;
        int n = e >> 3, c = e & 7;
        size_t off = (size_t)n*Kdim + kc0 + c*8;
        cpasync16(sbase + B_OFF + n*144 + c*16, B + off);
    }
}

// B-only load (K = DM)
__device__ __forceinline__ void load_b2(uint32_t bbase,
    const __half* B, int kc0, int tid)
{
#pragma unroll
    for (int g = 0; g < 4; g++) {
        int e = g*512 + tid;
        int n = e >> 3, c = e & 7;
        size_t off = (size_t)n*DM + kc0 + c*8;
        cpasync16(bbase + n*144 + c*16, B + off);
    }
}

__device__ __forceinline__ void mma_chunk(uint32_t aB, uint32_t bB,
    uint32_t aRow, uint32_t aKoff, uint32_t bRow, uint32_t bKoff,
    int nbase, float (*acc)[8][4])
{
#pragma unroll
    for (int k16 = 0; k16 < 4; k16++) {
        uint32_t ah[2][4];
        uint32_t ab = aB + aRow*144 + k16*32 + aKoff;
        ldsm4(ah[0], ab);
        ldsm4(ah[1], ab + 16*144);
#pragma unroll
        for (int np = 0; np < 4; np++) {
            uint32_t bh[4];
            ldsm4(bh, bB + (nbase + np*16 + bRow)*144 + k16*32 + bKoff);
#pragma unroll
            for (int mf = 0; mf < 2; mf++) {
                mma16816(acc[mf][2*np],   ah[mf], bh);
                mma16816(acc[mf][2*np+1], ah[mf], bh + 2);
            }
        }
    }
}

// ===================== generic GEMM (q / x / k / v) ========================
// epi: 0 = fp32 -> outf; 1 = half(+bias) -> outh
__global__ __launch_bounds__(512, 1) void tc_gemm(
    const __half* __restrict__ A, const __half* __restrict__ Bw,
    const float* __restrict__ bias,
    float* __restrict__ outf, __half* __restrict__ outh,
    int Kdim, int epi_mode)
{
    extern __shared__ char dsm[];
    uint32_t sb = smem_u32(dsm);
    int tid = threadIdx.x, lid = tid & 31, wid = tid >> 5;
    int tile = blockIdx.x;
    int mw = wid & 3, nw = wid >> 2;
    int mbase = mw*32, nbase = nw*64;

    uint32_t aRow  = mbase + (lid & 15);
    uint32_t aKoff = ((lid >> 4) & 1) * 16;
    uint32_t bRow  = (lid & 7) + ((lid >> 4) & 1) * 8;
    uint32_t bKoff = ((lid >> 3) & 1) * 16;

    float acc[2][8][4];
#pragma unroll
    for (int i = 0; i < 2; i++)
#pragma unroll
        for (int j = 0; j < 8; j++)
#pragma unroll
            for (int e = 0; e < 4; e++) acc[i][j][e] = 0.f;

    const int nst = Kdim >> 6;
    int pre = nst < 3 ? nst : 3;
    for (int i = 0; i < pre; i++) {
        load_chunk(sb + i*STG, A, Bw, tile, Kdim, i*64, tid);
        CP_COMMIT();
    }
    for (int s = 0; s < nst; s++) {
        if (s + 3 < nst) {
            load_chunk(sb + ((s+3)&3)*STG, A, Bw, tile, Kdim, (s+3)*64, tid);
            CP_COMMIT();
            cp_wait_dyn(3);
        } else {
            cp_wait_dyn(nst - 1 - s);
        }
        __syncthreads();
        uint32_t stb = sb + (s&3)*STG;
        mma_chunk(stb, stb + B_OFF, aRow, aKoff, bRow, bKoff, nbase, acc);
        __syncthreads();
    }

    float* eb = (float*)dsm;   // [128][264]
#pragma unroll
    for (int mf = 0; mf < 2; mf++)
#pragma unroll
        for (int nf = 0; nf < 8; nf++) {
            int m = mbase + mf*16 + (lid >> 2);
            int n = nbase + nf*8 + (lid & 3)*2;
            eb[m*264 + n]     = acc[mf][nf][0];
            eb[m*264 + n + 1] = acc[mf][nf][1];
            eb[(m+8)*264 + n]     = acc[mf][nf][2];
            eb[(m+8)*264 + n + 1] = acc[mf][nf][3];
        }
    __syncthreads();

    for (int i = tid; i < 128*256; i += 512) {
        int row = i >> 8, col = i & 255;
        float v = eb[row*264 + col];
        if (bias) v += bias[col];
        size_t o = (size_t)(tile*128 + row) * DM + col;
        if (epi_mode == 0) outf[o] = v;
        else               outh[o] = __float2half_rn(v);
    }
}

// ===================== posh: h-gen -> pos = h@d2 -> epi3 ===================
// smem: h slots 4x18432 [0,73728); B dbl 2x36864 [73728,147456)
// sidx @147456 (512); sdel @147968 (2048)
// epilogue eb fp32 [128][264] @0 (135168, over dead h/B regions)
__global__ __launch_bounds__(512, 1) void posh_kernel(
    const float* __restrict__ xyz, const float* __restrict__ query,
    const float* __restrict__ d1w, const float* __restrict__ d1b,
    const float* __restrict__ d2b,
    const float* __restrict__ qv, const float* __restrict__ kpt,
    __half* __restrict__ outa, __half* __restrict__ outp)
{
    extern __shared__ char dsm[];
    uint32_t sb = smem_u32(dsm);
    int tid = threadIdx.x, lid = tid & 31, wid = tid >> 5;
    int tile = blockIdx.x;
    int bm0 = tile * 8, b = bm0 >> 11;
    int mw = wid & 3, nw = wid >> 2;
    int mbase = mw*32, nbase = nw*64;

    uint32_t aRow  = mbase + (lid & 15);
    uint32_t aKoff = ((lid >> 4) & 1) * 16;
    uint32_t bRow  = (lid & 7) + ((lid >> 4) & 1) * 8;
    uint32_t bKoff = ((lid >> 3) & 1) * 16;

    int*   sidx = (int*)(dsm + 147456);
    float* sdel = (float*)(dsm + 147968);   // [128][4]

    // prefetch B(d2) chunks 0,1 (overlaps h generation)
    load_b2(sb + SM_B2,         w_d2, 0,  tid); CP_COMMIT();
    load_b2(sb + SM_B2 + 36864, w_d2, 64, tid); CP_COMMIT();

    if (tid < 128) sidx[tid] = g_knn[(bm0 + (tid >> 4))*16 + (tid & 15)];
    __syncthreads();
    if (tid < 128) {
        int r = tid, bm = bm0 + (r >> 4);
        const float* qp = query + (size_t)bm*131;
        const float* xp = xyz + ((size_t)b*Np + sidx[r])*3;
        sdel[r*4+0] = qp[0] - xp[0];
        sdel[r*4+1] = qp[1] - xp[1];
        sdel[r*4+2] = qp[2] - xp[2];
    }
    __syncthreads();

    // h = relu(delta@d1 + d1b) -> fp16 into h slots
    for (int i = tid; i < 128*256; i += 512) {
        int row = i >> 8, col = i & 255;
        float v = fmaf(sdel[row*4+2], d1w[512+col],
                  fmaf(sdel[row*4+1], d1w[256+col],
                  fmaf(sdel[row*4+0], d1w[col], d1b[col])));
        v = fmaxf(v, 0.f);
        int slot = col >> 6;
        *(__half*)(dsm + slot*18432 + row*144 + (col & 63)*2) = __float2half_rn(v);
    }
    __syncthreads();

    float acc[2][8][4];
#pragma unroll
    for (int i = 0; i < 2; i++)
#pragma unroll
        for (int j = 0; j < 8; j++)
#pragma unroll
            for (int e = 0; e < 4; e++) acc[i][j][e] = 0.f;

    // pos = h @ d2 (dbl-buffered B)
    for (int c4 = 0; c4 < 4; c4++) {
        if (c4 < 3) { CP_WAIT(1); } else { CP_WAIT(0); }
        __syncthreads();
        mma_chunk(sb + c4*18432, sb + SM_B2 + (c4&1)*36864,
                  aRow, aKoff, bRow, bKoff, nbase, acc);
        __syncthreads();
        if (c4 + 2 < 4) {
            load_b2(sb + SM_B2 + (c4&1)*36864, w_d2, (c4+2)*64, tid);
            CP_COMMIT();
        }
    }

    // epilogue: pos(+d2b) half -> outp ; a = q - k[gather] + pos -> outa
    float* eb = (float*)dsm;   // [128][264] (over dead h/B regions)
#pragma unroll
    for (int mf = 0; mf < 2; mf++)
#pragma unroll
        for (int nf = 0; nf < 8; nf++) {
            int m = mbase + mf*16 + (lid >> 2);
            int n = nbase + nf*8 + (lid & 3)*2;
            eb[m*264 + n]     = acc[mf][nf][0];
            eb[m*264 + n + 1] = acc[mf][nf][1];
            eb[(m+8)*264 + n]     = acc[mf][nf][2];
            eb[(m+8)*264 + n + 1] = acc[mf][nf][3];
        }
    __syncthreads();

    for (int i = tid; i < 128*256; i += 512) {
        int row = i >> 8, col = i & 255;
        float v = eb[row*264 + col] + d2b[col];
        size_t o = (size_t)(tile*128 + row) * DM + col;
        outp[o] = __float2half_rn(v);
        int bm = bm0 + (row >> 4);
        int idx = sidx[row];
        float a = qv[(size_t)bm*DM + col]
                - kpt[((size_t)b*Np + idx)*DM + col] + v;
        outa[o] = __float2half_rn(a);
    }
}

// ===================== fused g1 -> g2 -> softmax/V/fc2/residual =============
__global__ __launch_bounds__(512, 1) void g1g2_fused(
    const __half* __restrict__ A,
    const __half* __restrict__ G1, const float* __restrict__ g1b,
    const __half* __restrict__ G2, const float* __restrict__ g2b,
    const float* __restrict__ fc2w, const float* __restrict__ fc2b,
    const float* __restrict__ query,
    const float* __restrict__ vpt, const __half* __restrict__ pos,
    float* __restrict__ out)
{
    extern __shared__ char dsm[];
    uint32_t sb = smem_u32(dsm);
    int tid = threadIdx.x, lid = tid & 31, wid = tid >> 5;
    int tile = blockIdx.x;
    int mw = wid & 3, nw = wid >> 2;
    int mbase = mw*32, nbase = nw*64;

    uint32_t aRow  = mbase + (lid & 15);
    uint32_t aKoff = ((lid >> 4) & 1) * 16;
    uint32_t bRow  = (lid & 7) + ((lid >> 4) & 1) * 8;
    uint32_t bKoff = ((lid >> 3) & 1) * 16;

    float acc[2][8][4];
#pragma unroll
    for (int i = 0; i < 2; i++)
#pragma unroll
        for (int j = 0; j < 8; j++)
#pragma unroll
            for (int e = 0; e < 4; e++) acc[i][j][e] = 0.f;

    // ---------------- loop1: t_pre = a @ g1 (K = 256, 4-stage) -------------
    for (int i = 0; i < 3; i++) {
        load_chunk(sb + i*STG, A, G1, tile, DM, i*64, tid);
        CP_COMMIT();
    }
    for (int s = 0; s < 4; s++) {
        if (s == 0) {
            load_chunk(sb + 3*STG, A, G1, tile, DM, 192, tid);
            CP_COMMIT();
            CP_WAIT(3);
        } else {
            cp_wait_dyn(3 - s);
        }
        __syncthreads();
        uint32_t stb = sb + (s&3)*STG;
        mma_chunk(stb, stb + B_OFF, aRow, aKoff, bRow, bKoff, nbase, acc);
        __syncthreads();
    }
    // all smem dead; acc holds t_pre

    // ---- prefetch g2 B chunks 0,1 into double buffers (dead region)
    load_b2(sb + SM_B2,         G2, 0,  tid); CP_COMMIT();
    load_b2(sb + SM_B2 + 36864, G2, 64, tid); CP_COMMIT();

    // ---- stage ALL FOUR t chunks from live acc (warp-group nw -> slot nw)
    {
        char* tA = dsm + nw*18432;
#pragma unroll
        for (int mf = 0; mf < 2; mf++)
#pragma unroll
            for (int nf = 0; nf < 8; nf++) {
                int r = mbase + mf*16 + (lid >> 2);
                int c = nf*8 + (lid & 3)*2;
                int gc = nbase + c;
                float v0 = fmaxf(acc[mf][nf][0] + g1b[gc],   0.f);
                float v1 = fmaxf(acc[mf][nf][1] + g1b[gc+1], 0.f);
                float v2 = fmaxf(acc[mf][nf][2] + g1b[gc],   0.f);
                float v3 = fmaxf(acc[mf][nf][3] + g1b[gc+1], 0.f);
                __half2 hp;
                hp.x = __float2half_rn(v0); hp.y = __float2half_rn(v1);
                *(uint32_t*)(tA + r*144 + c*2) = *(uint32_t*)&hp;
                hp.x = __float2half_rn(v2); hp.y = __float2half_rn(v3);
                *(uint32_t*)(tA + (r+8)*144 + c*2) = *(uint32_t*)&hp;
            }
    }

#pragma unroll
    for (int i = 0; i < 2; i++)
#pragma unroll
        for (int j = 0; j < 8; j++)
#pragma unroll
            for (int e = 0; e < 4; e++) acc[i][j][e] = 0.f;

    // ---------------- loop2: attn_pre = t @ g2 (K = 256, dbl-buffered B) ---
    for (int c4 = 0; c4 < 4; c4++) {
        if (c4 < 3) { CP_WAIT(1); } else { CP_WAIT(0); }
        __syncthreads();
        mma_chunk(sb + c4*18432, sb + SM_B2 + (c4&1)*36864,
                  aRow, aKoff, bRow, bKoff, nbase, acc);
        __syncthreads();
        if (c4 + 2 < 4) {
            load_b2(sb + SM_B2 + (c4&1)*36864, G2, (c4+2)*64, tid);
            CP_COMMIT();
        }
    }

    // ---------------- epilogue: stage attn_pre, softmax, V, fc2, residual ---
    float* eb   = (float*)dsm;                 // [128][264]  (135168 B)
    float* sres = (float*)(dsm + 139264);      // [8][256]    (8192 B)
    int*   sidx = (int*)  (dsm + 147456);      // [128]
#pragma unroll
    for (int mf = 0; mf < 2; mf++)
#pragma unroll
        for (int nf = 0; nf < 8; nf++) {
            int m = mbase + mf*16 + (lid >> 2);
            int n = nbase + nf*8 + (lid & 3)*2;
            eb[m*264 + n]     = acc[mf][nf][0];
            eb[m*264 + n + 1] = acc[mf][nf][1];
            eb[(m+8)*264 + n]     = acc[mf][nf][2];
            eb[(m+8)*264 + n + 1] = acc[mf][nf][3];
        }
    int bm0 = tile * 8;
    if (tid < 128) sidx[tid] = g_knn[(bm0 + (tid >> 4))*16 + (tid & 15)];
    __syncthreads();

    {
        int qq = tid >> 6, c0 = tid & 63;
        int bm = bm0 + qq, b = bm >> 11;
        float* attn_out = out + RES_ELEMS + (size_t)bm*16*DM;
#pragma unroll
        for (int jj = 0; jj < 4; jj++) {
            int col = c0 + 64*jj;
            float bb = g2b[col];
            float ap[16];
#pragma unroll
            for (int j = 0; j < 16; j++)
                ap[j] = (eb[(qq*16 + j)*264 + col] + bb) * 0.0625f;
            float mx = ap[0];
#pragma unroll
            for (int j = 1; j < 16; j++) mx = fmaxf(mx, ap[j]);
            float s = 0.f;
#pragma unroll
            for (int j = 0; j < 16; j++) { ap[j] = __expf(ap[j] - mx); s += ap[j]; }
            float inv = 1.0f / s;
            float racc = 0.f;
#pragma unroll
            for (int j = 0; j < 16; j++) {
                float a = ap[j] * inv;
                attn_out[j*DM + col] = a;
                float vv = vpt[((size_t)b*Np + sidx[qq*16 + j])*DM + col];
                float pp = __half2float(pos[((size_t)(tile*128 + qq*16 + j))*DM + col]);
                racc = fmaf(a, vv + pp, racc);
            }
            sres[qq*256 + col] = racc;
        }
    }
    __syncthreads();

    for (int o = tid; o < 8*DP; o += 512) {
        int qq = o >> 7, c = o & 127;
        float acc2 = fc2b[c];
        const float* sr = sres + qq*256;
#pragma unroll 4
        for (int k = 0; k < DM; k++) acc2 = fmaf(sr[k], fc2w[k*DP + c], acc2);
        int bm = bm0 + qq;
        out[(size_t)bm*DP + c] = acc2 + query[(size_t)bm*131 + 3 + c];
    }
}

// ===================== launch =====================
extern "C" void kernel_launch(void* const* d_in, const int* in_sizes, int n_in,
                              void* d_out, int out_size) {
    const float* xyz   = (const float*)d_in[0];
    const float* feat  = (const float*)d_in[1];
    const float* query = (const float*)d_in[2];
    const float* fc1w  = (const float*)d_in[3];
    const float* fc1b  = (const float*)d_in[4];
    const float* fc2w  = (const float*)d_in[5];
    const float* fc2b  = (const float*)d_in[6];
    const float* d1w   = (const float*)d_in[7];
    const float* d1b   = (const float*)d_in[8];
    const float* d2w   = (const float*)d_in[9];
    const float* d2b   = (const float*)d_in[10];
    const float* g1w   = (const float*)d_in[11];
    const float* g1b   = (const float*)d_in[12];
    const float* g2w   = (const float*)d_in[13];
    const float* g2b   = (const float*)d_in[14];
    const float* wq    = (const float*)d_in[15];
    const float* wk    = (const float*)d_in[16];
    const float* wv    = (const float*)d_in[17];
    float* out = (float*)d_out;

    static int smem_set = 0;
    if (!smem_set) {
        cudaFuncSetAttribute(tc_gemm,     cudaFuncAttributeMaxDynamicSharedMemorySize, SMEM_TOTAL);
        cudaFuncSetAttribute(posh_kernel, cudaFuncAttributeMaxDynamicSharedMemorySize, SMEM_TOTAL);
        cudaFuncSetAttribute(g1g2_fused,  cudaFuncAttributeMaxDynamicSharedMemorySize, SMEM_TOTAL);
        smem_set = 1;
    }

    __half *p_wq, *p_wf1, *p_wk, *p_wv, *p_wg1, *p_wg2;
    cudaGetSymbolAddress((void**)&p_wq,  w_q);
    cudaGetSymbolAddress((void**)&p_wf1, w_f1);
    cudaGetSymbolAddress((void**)&p_wk,  w_k);
    cudaGetSymbolAddress((void**)&p_wv,  w_v);
    cudaGetSymbolAddress((void**)&p_wg1, w_g1);
    cudaGetSymbolAddress((void**)&p_wg2, w_g2);
    __half *p_wd2;
    cudaGetSymbolAddress((void**)&p_wd2, w_d2);
    float *p_q, *p_kp, *p_vp;
    __half *p_pos, *p_qf, *p_fs, *p_xp, *p_a;
    cudaGetSymbolAddress((void**)&p_q,   g_q);
    cudaGetSymbolAddress((void**)&p_kp,  g_kpt);
    cudaGetSymbolAddress((void**)&p_vp,  g_vpt);
    cudaGetSymbolAddress((void**)&p_pos, g_pos);
    cudaGetSymbolAddress((void**)&p_qf,  g_qf);
    cudaGetSymbolAddress((void**)&p_fs,  g_fs);
    cudaGetSymbolAddress((void**)&p_xp,  g_xp);
    cudaGetSymbolAddress((void**)&p_a,   g_a);

    knn_kernel<<<BM/8, 256>>>(xyz, query);

    wprep_kernel<<<DP, 256>>>(wq,   p_wq,  DP);
    wprep_kernel<<<DP, 256>>>(fc1w, p_wf1, DP);
    wprep_kernel<<<DM, 256>>>(wk,   p_wk,  DM);
    wprep_kernel<<<DM, 256>>>(wv,   p_wv,  DM);
    wprep_kernel<<<DM, 256>>>(d2w,  p_wd2, DM);
    wprep_kernel<<<DM, 256>>>(g1w,  p_wg1, DM);
    wprep_kernel<<<DM, 256>>>(g2w,  p_wg2, DM);

    qcvt_kernel<<<BM*DP/256, 256>>>(query, p_qf);
    fcvt_kernel<<<NPT*DP/256, 256>>>(feat, p_fs);

    // q = query_f @ wq                     (8192 rows, fp32 -> g_q)
    tc_gemm<<<BM/128, 512, SMEM_TOTAL>>>(p_qf, p_wq,
        nullptr, p_q, nullptr, DP, 0);
    // x_pt = feat @ fc1 + b                (32768 rows, half)
    tc_gemm<<<NPT/128, 512, SMEM_TOTAL>>>(p_fs, p_wf1,
        fc1b, nullptr, p_xp, DP, 1);
    // k_pt = x_pt @ wk                     (32768 rows, fp32)
    tc_gemm<<<NPT/128, 512, SMEM_TOTAL>>>(p_xp, p_wk,
        nullptr, p_kp, nullptr, DM, 0);
    // v_pt = x_pt @ wv                     (32768 rows, fp32)
    tc_gemm<<<NPT/128, 512, SMEM_TOTAL>>>(p_xp, p_wv,
        nullptr, p_vp, nullptr, DM, 0);
    // posh: h-gen; pos = h@d2 + b (half); a = q - k[gather] + pos (half)
    posh_kernel<<<NROW/128, 512, SMEM_TOTAL>>>(xyz, query, d1w, d1b,
        d2b, p_q, p_kp, p_a, p_pos);
    // fused: t = relu(a@g1+b); attn_pre = t@g2+b; softmax; res; fc2; residual
    g1g2_fused<<<NROW/128, 512, SMEM_TOTAL>>>(p_a, p_wg1, g1b,
        p_wg2, g2b, fc2w, fc2b, query, p_vp, p_pos, out);
}